// round 10
// baseline (speedup 1.0000x reference)
#include <cuda_runtime.h>
#include <math.h>
#include <limits.h>

// WARP loss, R10: two-probe 20KB/20KB scan (1.49 serialized rounds/CTA ->
// measured ~5.9TB/s regime) + lazy 16-candidate gather (fallback prob ~0.3%)
// + neg-index prefetch at entry (kills one dependent DRAM trip in the tail).
// Traffic ledger: scan 122MB + gathers ~8MB + neg 2MB ~= 132MB.

#define NT 256
#define P_VEC 5          // 5 float4/thread per probe = 20KB (NT=256)
#define BATCH1 16        // trials gathered eagerly

__global__ __launch_bounds__(NT, 8)
void warp_loss_kernel(const float* __restrict__ input,
                      const float* __restrict__ target,
                      const int*   __restrict__ neg,
                      float* __restrict__ out,
                      int Y, int T) {
    const int row  = blockIdx.x;
    const int tid  = threadIdx.x;
    const int lane = tid & 31;
    const int wid  = tid >> 5;
    const float* irow = input  + (size_t)row * Y;
    const float* trow = target + (size_t)row * Y;

    __shared__ float sc_sh[128];      // candidate scores (fallback path)
    __shared__ float s_pscore;        // positive score
    __shared__ int   s_first1;        // first accepted among trials 0..BATCH1-1
    __shared__ int   s_first_w[4];    // per-warp mins (fallback)

    // --- Phase 0: prefetch first BATCH1 neg indices (64B, independent) ---
    int c_pre = 0;
    if (wid == 0 && lane < BATCH1)
        c_pre = __ldg(&neg[(size_t)row * T + lane]);

    const int nvec = Y >> 2;                        // 2500 for Y=10000
    const float4* tv = reinterpret_cast<const float4*>(trow);
    const float4 zero4 = make_float4(0.f, 0.f, 0.f, 0.f);

    // --- Probe 1: first 20KB, all loads in flight before any test ---
    {
        float4 v[P_VEC]; int idx[P_VEC];
#pragma unroll
        for (int k = 0; k < P_VEC; k++) {
            idx[k] = k * NT + tid;
            v[k] = (idx[k] < nvec) ? __ldg(&tv[idx[k]]) : zero4;
        }
        int p = -1;
#pragma unroll
        for (int k = 0; k < P_VEC; k++) {
            if (v[k].x != 0.0f) p = 4 * idx[k];
            if (v[k].y != 0.0f) p = 4 * idx[k] + 1;
            if (v[k].z != 0.0f) p = 4 * idx[k] + 2;
            if (v[k].w != 0.0f) p = 4 * idx[k] + 3;
        }
        if (p >= 0) s_pscore = __ldg(&irow[p]);
        if (!__syncthreads_or(p >= 0)) {
            // --- Probe 2: remaining ~19.5KB ---
            float4 w[P_VEC]; int jdx[P_VEC];
#pragma unroll
            for (int k = 0; k < P_VEC; k++) {
                jdx[k] = (P_VEC + k) * NT + tid;
                w[k] = (jdx[k] < nvec) ? __ldg(&tv[jdx[k]]) : zero4;
            }
            int q = -1;
#pragma unroll
            for (int k = 0; k < P_VEC; k++) {
                if (w[k].x != 0.0f) q = 4 * jdx[k];
                if (w[k].y != 0.0f) q = 4 * jdx[k] + 1;
                if (w[k].z != 0.0f) q = 4 * jdx[k] + 2;
                if (w[k].w != 0.0f) q = 4 * jdx[k] + 3;
            }
            for (int i = (nvec << 2) + tid; i < Y; i += NT)   // scalar tail
                if (trow[i] != 0.0f) q = i;
            if (q >= 0) s_pscore = __ldg(&irow[q]);
            __syncthreads();
        }
    }
    const float sp = s_pscore;

    // --- Batch 1: trials 0..15 (warp 0; indices already in registers) ---
    if (wid == 0) {
        float sc = 0.0f;
        bool acc = false;
        if (lane < BATCH1) {
            sc = __ldg(&irow[c_pre]);
            acc = (1.0f + sc - sp >= 0.0f);
        }
        const unsigned m = __ballot_sync(0xFFFFFFFFu, acc);
        const int first = m ? (__ffs(m) - 1) : INT_MAX;
        if (first != INT_MAX) {
            const float sn = __shfl_sync(0xFFFFFFFFu, sc, first);
            if (lane == 0) {
                s_first1 = first;
                const int num_trials = first + 1;
                const float L = logf((float)((Y - 1) / num_trials));
                atomicAdd(out, L * (1.0f - sp + sn));
            }
        } else if (lane == 0) {
            s_first1 = INT_MAX;
        }
    }
    __syncthreads();

    // --- Fallback (rare, ~0.3%): trials BATCH1..T-1 on threads BATCH1..T-1 ---
    if (s_first1 == INT_MAX && T > BATCH1) {
        bool acc = false;
        if (tid >= BATCH1 && tid < T) {
            const int c = __ldg(&neg[(size_t)row * T + tid]);
            const float sc = __ldg(&irow[c]);
            sc_sh[tid] = sc;
            acc = (1.0f + sc - sp >= 0.0f);
        }
        const unsigned m = __ballot_sync(0xFFFFFFFFu, acc);
        if (lane == 0) s_first_w[wid] = m ? (wid * 32 + __ffs(m) - 1) : INT_MAX;
        __syncthreads();
        if (tid == 0) {
            int first = s_first_w[0];
            first = min(first, s_first_w[1]);
            first = min(first, s_first_w[2]);
            first = min(first, s_first_w[3]);
            if (first != INT_MAX) {
                const int num_trials = first + 1;
                const float L = logf((float)((Y - 1) / num_trials));
                atomicAdd(out, L * (1.0f - sp + sc_sh[first]));
            }
        }
    }
}

extern "C" void kernel_launch(void* const* d_in, const int* in_sizes, int n_in,
                              void* d_out, int out_size) {
    const float* input  = (const float*)d_in[0];
    const float* target = (const float*)d_in[1];
    const int*   neg    = (const int*)d_in[2];
    float* out = (float*)d_out;

    const int Y = 10000;                 // fixed by problem spec
    const int B = in_sizes[0] / Y;       // 4096
    const int T = in_sizes[2] / B;       // 128

    cudaMemsetAsync(out, 0, (size_t)out_size * sizeof(float), 0);
    warp_loss_kernel<<<B, NT>>>(input, target, neg, out, Y, T);
}